// round 2
// baseline (speedup 1.0000x reference)
#include <cuda_runtime.h>
#include <math.h>

#define NN_NODES 4096
#define BB 64
#define DIN 64
#define DH 64
#define CC 128              // DIN + DH
#define EE 16
#define BCOLS (BB * CC)     // 8192

// ---------------- device scratch (module-load allocated, no runtime allocs) ----
__device__ float g_S[(size_t)NN_NODES * NN_NODES];      // 64 MB  supports
__device__ float g_CAT[(size_t)NN_NODES * BCOLS];       // 128 MB concat, (n, b, c)
__device__ float g_XG[(size_t)NN_NODES * BCOLS];        // 128 MB S @ CAT, (n, b, c)
__device__ float g_W[(size_t)NN_NODES * CC * CC];       // 256 MB per-node weights
__device__ float g_BIAS[(size_t)NN_NODES * CC];         // 2 MB per-node bias
__device__ float g_ZR[(size_t)NN_NODES * BCOLS];        // 128 MB z_r, (n, b, j)

// ---------------- supports = softmax(relu(NE @ NE^T)) per row -------------------
__global__ __launch_bounds__(256) void k_supports(const float* __restrict__ ne) {
    int n = blockIdx.x, tid = threadIdx.x;
    __shared__ float e[EE];
    __shared__ float redm[8], reds[8];
    if (tid < EE) e[tid] = ne[n * EE + tid];
    __syncthreads();

    float vals[16];
    float mx = 0.0f;   // relu => all values >= 0
    #pragma unroll
    for (int j = 0; j < 16; j++) {
        int m = tid + j * 256;
        const float4* p = reinterpret_cast<const float4*>(ne + m * EE);
        float4 v0 = p[0], v1 = p[1], v2 = p[2], v3 = p[3];
        float d = e[0] * v0.x + e[1] * v0.y + e[2] * v0.z + e[3] * v0.w
                + e[4] * v1.x + e[5] * v1.y + e[6] * v1.z + e[7] * v1.w
                + e[8] * v2.x + e[9] * v2.y + e[10] * v2.z + e[11] * v2.w
                + e[12] * v3.x + e[13] * v3.y + e[14] * v3.z + e[15] * v3.w;
        d = fmaxf(d, 0.0f);
        vals[j] = d;
        mx = fmaxf(mx, d);
    }
    #pragma unroll
    for (int o = 16; o > 0; o >>= 1) mx = fmaxf(mx, __shfl_xor_sync(0xffffffffu, mx, o));
    if ((tid & 31) == 0) redm[tid >> 5] = mx;
    __syncthreads();
    mx = redm[0];
    #pragma unroll
    for (int w = 1; w < 8; w++) mx = fmaxf(mx, redm[w]);

    float s = 0.0f;
    #pragma unroll
    for (int j = 0; j < 16; j++) { vals[j] = __expf(vals[j] - mx); s += vals[j]; }
    #pragma unroll
    for (int o = 16; o > 0; o >>= 1) s += __shfl_xor_sync(0xffffffffu, s, o);
    if ((tid & 31) == 0) reds[tid >> 5] = s;
    __syncthreads();
    s = 0.0f;
    #pragma unroll
    for (int w = 0; w < 8; w++) s += reds[w];
    float inv = 1.0f / s;
    #pragma unroll
    for (int j = 0; j < 16; j++)
        g_S[(size_t)n * NN_NODES + tid + j * 256] = vals[j] * inv;
}

// ---------------- per-node weights: g_W[n, :] = NE[n,:] @ Wpool ------------------
// IO = I*O (flattened last two dims of the pool). Writes coalesced over io.
__global__ __launch_bounds__(256) void k_mkweights(const float* __restrict__ ne,
                                                   const float* __restrict__ wp,
                                                   int IO) {
    int io = blockIdx.x * 256 + threadIdx.x;
    float wv[EE];
    #pragma unroll
    for (int d = 0; d < EE; d++) wv[d] = wp[(size_t)d * IO + io];
    __shared__ float sne[128 * EE];
    for (int n0 = 0; n0 < NN_NODES; n0 += 128) {
        __syncthreads();
        for (int t = threadIdx.x; t < 128 * EE; t += 256) sne[t] = ne[n0 * EE + t];
        __syncthreads();
        for (int nn = 0; nn < 128; nn++) {
            float v = 0.0f;
            #pragma unroll
            for (int d = 0; d < EE; d++) v += sne[nn * EE + d] * wv[d];
            g_W[(size_t)(n0 + nn) * IO + io] = v;
        }
    }
}

// ---------------- per-node bias: g_BIAS[n, o] = NE[n,:] @ bias_pool --------------
__global__ void k_bias(const float* __restrict__ ne, const float* __restrict__ bp, int O) {
    int n = blockIdx.x, o = threadIdx.x;
    float v = 0.0f;
    #pragma unroll
    for (int d = 0; d < EE; d++) v += ne[n * EE + d] * bp[d * O + o];
    g_BIAS[n * O + o] = v;
}

// ---------------- CAT1[n,b,c] = [x | state] --------------------------------------
__global__ __launch_bounds__(256) void k_cat1(const float* __restrict__ x,
                                              const float* __restrict__ st) {
    int n = blockIdx.x;
    #pragma unroll 2
    for (int idx = threadIdx.x; idx < BB * CC / 4; idx += 256) {
        int b = idx >> 5, c4 = idx & 31;
        float4 v;
        if (c4 < 16)
            v = *reinterpret_cast<const float4*>(x + ((size_t)b * NN_NODES + n) * DIN + (c4 << 2));
        else
            v = *reinterpret_cast<const float4*>(st + ((size_t)b * NN_NODES + n) * DH + ((c4 - 16) << 2));
        *reinterpret_cast<float4*>(g_CAT + (size_t)n * BCOLS + (idx << 2)) = v;
    }
}

// ---------------- CAT2[n,b,c] = [x | z*state] ------------------------------------
__global__ __launch_bounds__(256) void k_cat2(const float* __restrict__ x,
                                              const float* __restrict__ st) {
    int n = blockIdx.x;
    #pragma unroll 2
    for (int idx = threadIdx.x; idx < BB * CC / 4; idx += 256) {
        int b = idx >> 5, c4 = idx & 31;
        float4 v;
        if (c4 < 16) {
            v = *reinterpret_cast<const float4*>(x + ((size_t)b * NN_NODES + n) * DIN + (c4 << 2));
        } else {
            float4 z = *reinterpret_cast<const float4*>(g_ZR + (size_t)n * BCOLS + b * CC + ((c4 - 16) << 2));
            float4 s = *reinterpret_cast<const float4*>(st + ((size_t)b * NN_NODES + n) * DH + ((c4 - 16) << 2));
            v = make_float4(z.x * s.x, z.y * s.y, z.z * s.z, z.w * s.w);
        }
        *reinterpret_cast<float4*>(g_CAT + (size_t)n * BCOLS + (idx << 2)) = v;
    }
}

// ---------------- big SGEMM: g_XG = g_S (4096x4096) @ g_CAT (4096x8192) ----------
// 128x128 tiles, BK=8, 256 threads, 8x8 microtile, double-buffered smem.
__global__ __launch_bounds__(256) void k_sgemm() {
    const int K = NN_NODES;     // 4096
    const int NC = BCOLS;       // 8192
    __shared__ float As[2][8][128];
    __shared__ float Bs[2][8][128];

    int tid = threadIdx.x;
    int bx = blockIdx.x, by = blockIdx.y;

    int loadArow = tid >> 1, loadAcol = (tid & 1) * 4;
    int loadBrow = tid >> 5, loadBcol = (tid & 31) * 4;
    const float* Ap = g_S + (size_t)(by * 128 + loadArow) * K + loadAcol;
    const float* Bp = g_CAT + (size_t)loadBrow * NC + bx * 128 + loadBcol;

    int tr = (tid >> 4) * 8, tc = (tid & 15) * 8;
    float acc[8][8] = {};

    float4 a4 = *reinterpret_cast<const float4*>(Ap);
    float4 b4 = *reinterpret_cast<const float4*>(Bp);
    As[0][loadAcol + 0][loadArow] = a4.x;
    As[0][loadAcol + 1][loadArow] = a4.y;
    As[0][loadAcol + 2][loadArow] = a4.z;
    As[0][loadAcol + 3][loadArow] = a4.w;
    *reinterpret_cast<float4*>(&Bs[0][loadBrow][loadBcol]) = b4;
    __syncthreads();

    int buf = 0;
    const int NT = K / 8;       // 512
    for (int kt = 1; kt <= NT; kt++) {
        if (kt < NT) {
            a4 = *reinterpret_cast<const float4*>(Ap + kt * 8);
            b4 = *reinterpret_cast<const float4*>(Bp + (size_t)kt * 8 * NC);
        }
        #pragma unroll
        for (int k = 0; k < 8; k++) {
            float ar[8], br[8];
            *reinterpret_cast<float4*>(&ar[0]) = *reinterpret_cast<const float4*>(&As[buf][k][tr]);
            *reinterpret_cast<float4*>(&ar[4]) = *reinterpret_cast<const float4*>(&As[buf][k][tr + 4]);
            *reinterpret_cast<float4*>(&br[0]) = *reinterpret_cast<const float4*>(&Bs[buf][k][tc]);
            *reinterpret_cast<float4*>(&br[4]) = *reinterpret_cast<const float4*>(&Bs[buf][k][tc + 4]);
            #pragma unroll
            for (int i = 0; i < 8; i++)
                #pragma unroll
                for (int j = 0; j < 8; j++)
                    acc[i][j] += ar[i] * br[j];
        }
        if (kt < NT) {
            buf ^= 1;
            As[buf][loadAcol + 0][loadArow] = a4.x;
            As[buf][loadAcol + 1][loadArow] = a4.y;
            As[buf][loadAcol + 2][loadArow] = a4.z;
            As[buf][loadAcol + 3][loadArow] = a4.w;
            *reinterpret_cast<float4*>(&Bs[buf][loadBrow][loadBcol]) = b4;
            __syncthreads();
        }
    }

    float* Cp = g_XG + (size_t)(by * 128 + tr) * NC + bx * 128 + tc;
    #pragma unroll
    for (int i = 0; i < 8; i++) {
        *reinterpret_cast<float4*>(Cp + (size_t)i * NC) =
            make_float4(acc[i][0], acc[i][1], acc[i][2], acc[i][3]);
        *reinterpret_cast<float4*>(Cp + (size_t)i * NC + 4) =
            make_float4(acc[i][4], acc[i][5], acc[i][6], acc[i][7]);
    }
}

// ---------------- per-node gate GEMM + sigmoid: ZR[n,b,j] --------------------------
// Per block: X (64x128) @ W_n (128x128) + bias, sigmoid.
__global__ __launch_bounds__(256) void k_node_gate() {
    int n = blockIdx.x, tid = threadIdx.x;
    __shared__ float Xs[BB][132];
    __shared__ float Ws[16][132];

    #pragma unroll
    for (int p = 0; p < 8; p++) {
        int f = tid + p * 256;
        int b = f >> 5, i4 = (f & 31) << 2;
        *reinterpret_cast<float4*>(&Xs[b][i4]) =
            *reinterpret_cast<const float4*>(g_XG + (size_t)n * BCOLS + b * CC + i4);
    }

    int tb = (tid >> 4) << 2;   // 4 batch rows
    int tj = (tid & 15) << 3;   // 8 output cols
    float acc[4][8] = {};

    for (int i0 = 0; i0 < CC; i0 += 16) {
        __syncthreads();
        #pragma unroll
        for (int p = 0; p < 2; p++) {
            int f = tid + p * 256;
            int k = f >> 5, j4 = (f & 31) << 2;
            *reinterpret_cast<float4*>(&Ws[k][j4]) =
                *reinterpret_cast<const float4*>(g_W + (size_t)n * (CC * CC) + (i0 + k) * CC + j4);
        }
        __syncthreads();
        #pragma unroll
        for (int k = 0; k < 16; k++) {
            float a[4], bv[8];
            #pragma unroll
            for (int bb = 0; bb < 4; bb++) a[bb] = Xs[tb + bb][i0 + k];
            *reinterpret_cast<float4*>(&bv[0]) = *reinterpret_cast<const float4*>(&Ws[k][tj]);
            *reinterpret_cast<float4*>(&bv[4]) = *reinterpret_cast<const float4*>(&Ws[k][tj + 4]);
            #pragma unroll
            for (int bb = 0; bb < 4; bb++)
                #pragma unroll
                for (int jj = 0; jj < 8; jj++)
                    acc[bb][jj] += a[bb] * bv[jj];
        }
    }

    float bias[8];
    *reinterpret_cast<float4*>(&bias[0]) = *reinterpret_cast<const float4*>(g_BIAS + n * CC + tj);
    *reinterpret_cast<float4*>(&bias[4]) = *reinterpret_cast<const float4*>(g_BIAS + n * CC + tj + 4);
    #pragma unroll
    for (int bb = 0; bb < 4; bb++) {
        float y[8];
        #pragma unroll
        for (int jj = 0; jj < 8; jj++) {
            float v = acc[bb][jj] + bias[jj];
            y[jj] = 1.0f / (1.0f + __expf(-v));
        }
        float* dst = g_ZR + (size_t)n * BCOLS + (tb + bb) * CC + tj;
        *reinterpret_cast<float4*>(dst) = make_float4(y[0], y[1], y[2], y[3]);
        *reinterpret_cast<float4*>(dst + 4) = make_float4(y[4], y[5], y[6], y[7]);
    }
}

// ---------------- per-node update GEMM + tanh + GRU combine -> out -----------------
__global__ __launch_bounds__(256) void k_node_final(const float* __restrict__ st,
                                                    float* __restrict__ out) {
    int n = blockIdx.x, tid = threadIdx.x;
    __shared__ float Xs[BB][132];
    __shared__ float Ws[16][68];

    #pragma unroll
    for (int p = 0; p < 8; p++) {
        int f = tid + p * 256;
        int b = f >> 5, i4 = (f & 31) << 2;
        *reinterpret_cast<float4*>(&Xs[b][i4]) =
            *reinterpret_cast<const float4*>(g_XG + (size_t)n * BCOLS + b * CC + i4);
    }

    int tb = (tid >> 4) << 2;   // 4 batch rows
    int to = (tid & 15) << 2;   // 4 output cols
    float acc[4][4] = {};

    for (int i0 = 0; i0 < CC; i0 += 16) {
        __syncthreads();
        {
            int k = tid >> 4, o4 = (tid & 15) << 2;
            *reinterpret_cast<float4*>(&Ws[k][o4]) =
                *reinterpret_cast<const float4*>(g_W + (size_t)n * (CC * DH) + (i0 + k) * DH + o4);
        }
        __syncthreads();
        #pragma unroll
        for (int k = 0; k < 16; k++) {
            float a[4], bv[4];
            #pragma unroll
            for (int bb = 0; bb < 4; bb++) a[bb] = Xs[tb + bb][i0 + k];
            *reinterpret_cast<float4*>(&bv[0]) = *reinterpret_cast<const float4*>(&Ws[k][to]);
            #pragma unroll
            for (int bb = 0; bb < 4; bb++)
                #pragma unroll
                for (int oo = 0; oo < 4; oo++)
                    acc[bb][oo] += a[bb] * bv[oo];
        }
    }

    float bias[4];
    *reinterpret_cast<float4*>(&bias[0]) = *reinterpret_cast<const float4*>(g_BIAS + n * DH + to);
    #pragma unroll
    for (int bb = 0; bb < 4; bb++) {
        int b = tb + bb;
        float4 r4 = *reinterpret_cast<const float4*>(g_ZR + (size_t)n * BCOLS + b * CC + DH + to);
        float4 s4 = *reinterpret_cast<const float4*>(st + ((size_t)b * NN_NODES + n) * DH + to);
        float hc0 = tanhf(acc[bb][0] + bias[0]);
        float hc1 = tanhf(acc[bb][1] + bias[1]);
        float hc2 = tanhf(acc[bb][2] + bias[2]);
        float hc3 = tanhf(acc[bb][3] + bias[3]);
        float4 h;
        h.x = r4.x * s4.x + (1.0f - r4.x) * hc0;
        h.y = r4.y * s4.y + (1.0f - r4.y) * hc1;
        h.z = r4.z * s4.z + (1.0f - r4.z) * hc2;
        h.w = r4.w * s4.w + (1.0f - r4.w) * hc3;
        *reinterpret_cast<float4*>(out + ((size_t)b * NN_NODES + n) * DH + to) = h;
    }
}

// ---------------- launch ------------------------------------------------------------
extern "C" void kernel_launch(void* const* d_in, const int* in_sizes, int n_in,
                              void* d_out, int out_size) {
    const float* x   = (const float*)d_in[0];
    const float* st  = (const float*)d_in[1];
    const float* ne  = (const float*)d_in[2];
    const float* gwp = (const float*)d_in[3];
    const float* gbp = (const float*)d_in[4];
    const float* uwp = (const float*)d_in[5];
    const float* ubp = (const float*)d_in[6];
    float* out = (float*)d_out;

    // supports + gate weights/bias (independent of activations)
    k_supports<<<NN_NODES, 256>>>(ne);
    k_mkweights<<<(CC * CC) / 256, 256>>>(ne, gwp, CC * CC);
    k_bias<<<NN_NODES, CC>>>(ne, gbp, CC);

    // gate path
    k_cat1<<<NN_NODES, 256>>>(x, st);
    k_sgemm<<<dim3(BCOLS / 128, NN_NODES / 128), 256>>>();
    k_node_gate<<<NN_NODES, 256>>>();

    // update path
    k_cat2<<<NN_NODES, 256>>>(x, st);
    k_mkweights<<<(CC * DH) / 256, 256>>>(ne, uwp, CC * DH);
    k_bias<<<NN_NODES, DH>>>(ne, ubp, DH);
    k_sgemm<<<dim3(BCOLS / 128, NN_NODES / 128), 256>>>();
    k_node_final<<<NN_NODES, 256>>>(st, out);
}

// round 4
// speedup vs baseline: 2.8075x; 2.8075x over previous
#include <cuda_runtime.h>
#include <cuda_bf16.h>
#include <math.h>
#include <stdint.h>

#define NN 4096
#define BB 64
#define DIN 64
#define DH 64
#define CC 128              // DIN + DH
#define EE 16
#define XGPITCH (BB * CC)   // 8192

// ================= device scratch (no runtime allocs) ==========================
__device__ __nv_bfloat16 g_Shi[(size_t)NN * NN];     // 32 MB supports hi (A operand)
__device__ __nv_bfloat16 g_Slo[(size_t)NN * NN];     // 32 MB supports lo
__device__ __nv_bfloat16 g_BXhi[(size_t)NN * NN];    // 32 MB x^T hi    [j=b*64+c][m]
__device__ __nv_bfloat16 g_BXlo[(size_t)NN * NN];    // 32 MB x^T lo
__device__ __nv_bfloat16 g_BShi[(size_t)NN * NN];    // 32 MB state^T / (z*state)^T hi
__device__ __nv_bfloat16 g_BSlo[(size_t)NN * NN];    // 32 MB
__device__ float g_XG[(size_t)NN * XGPITCH];         // 128 MB [n][b][128]
__device__ float g_W[(size_t)NN * CC * CC];          // 256 MB per-node weights
__device__ float g_BIAS[(size_t)NN * CC];            // 2 MB
__device__ float g_ZR[(size_t)NN * XGPITCH];         // 128 MB z_r [n][b*128+j]

// ================= PTX helpers (sm_80-level only; NO tcgen05) ====================
__device__ __forceinline__ uint32_t smem_u32(const void* p) {
    uint32_t a;
    asm("{ .reg .u64 t; cvta.to.shared.u64 t, %1; cvt.u32.u64 %0, t; }" : "=r"(a) : "l"(p));
    return a;
}
__device__ __forceinline__ void cpa16(uint32_t dst, const void* src) {
    asm volatile("cp.async.cg.shared.global [%0], [%1], 16;" :: "r"(dst), "l"(src));
}
#define CP_COMMIT() asm volatile("cp.async.commit_group;" ::: "memory")
#define CP_WAIT1()  asm volatile("cp.async.wait_group 1;" ::: "memory")

#define LDSM4(r0, r1, r2, r3, addr) \
    asm volatile("ldmatrix.sync.aligned.m8n8.x4.shared.b16 {%0,%1,%2,%3}, [%4];" \
        : "=r"(r0), "=r"(r1), "=r"(r2), "=r"(r3) : "r"(addr))

#define MMA_BF16(c, a, b) \
    asm volatile("mma.sync.aligned.m16n8k16.row.col.f32.bf16.bf16.f32 " \
        "{%0,%1,%2,%3}, {%4,%5,%6,%7}, {%8,%9}, {%0,%1,%2,%3};" \
        : "+f"((c)[0]), "+f"((c)[1]), "+f"((c)[2]), "+f"((c)[3]) \
        : "r"((a)[0]), "r"((a)[1]), "r"((a)[2]), "r"((a)[3]), \
          "r"((b)[0]), "r"((b)[1]))

// ================ supports = softmax(relu(NE @ NE^T)) -> bf16 hi/lo ==============
__global__ __launch_bounds__(256) void k_supports(const float* __restrict__ ne) {
    int n = blockIdx.x, tid = threadIdx.x;
    __shared__ float e[EE];
    __shared__ float redm[8], reds[8];
    if (tid < EE) e[tid] = ne[n * EE + tid];
    __syncthreads();

    float vals[16];
    float mx = 0.0f;
    #pragma unroll
    for (int j = 0; j < 16; j++) {
        int m = tid + j * 256;
        const float4* p = reinterpret_cast<const float4*>(ne + m * EE);
        float4 v0 = p[0], v1 = p[1], v2 = p[2], v3 = p[3];
        float d = e[0]*v0.x + e[1]*v0.y + e[2]*v0.z + e[3]*v0.w
                + e[4]*v1.x + e[5]*v1.y + e[6]*v1.z + e[7]*v1.w
                + e[8]*v2.x + e[9]*v2.y + e[10]*v2.z + e[11]*v2.w
                + e[12]*v3.x + e[13]*v3.y + e[14]*v3.z + e[15]*v3.w;
        d = fmaxf(d, 0.0f);
        vals[j] = d;
        mx = fmaxf(mx, d);
    }
    #pragma unroll
    for (int o = 16; o > 0; o >>= 1) mx = fmaxf(mx, __shfl_xor_sync(0xffffffffu, mx, o));
    if ((tid & 31) == 0) redm[tid >> 5] = mx;
    __syncthreads();
    mx = redm[0];
    #pragma unroll
    for (int w = 1; w < 8; w++) mx = fmaxf(mx, redm[w]);

    float s = 0.0f;
    #pragma unroll
    for (int j = 0; j < 16; j++) { vals[j] = __expf(vals[j] - mx); s += vals[j]; }
    #pragma unroll
    for (int o = 16; o > 0; o >>= 1) s += __shfl_xor_sync(0xffffffffu, s, o);
    if ((tid & 31) == 0) reds[tid >> 5] = s;
    __syncthreads();
    s = 0.0f;
    #pragma unroll
    for (int w = 0; w < 8; w++) s += reds[w];
    float inv = 1.0f / s;
    #pragma unroll
    for (int j = 0; j < 16; j++) {
        float v = vals[j] * inv;
        __nv_bfloat16 h = __float2bfloat16(v);
        size_t o = (size_t)n * NN + tid + j * 256;
        g_Shi[o] = h;
        g_Slo[o] = __float2bfloat16(v - __bfloat162float(h));
    }
}

// ================ per-node weights / bias ========================================
__global__ __launch_bounds__(256) void k_mkweights(const float* __restrict__ ne,
                                                   const float* __restrict__ wp,
                                                   int IO) {
    int io = blockIdx.x * 256 + threadIdx.x;
    float wv[EE];
    #pragma unroll
    for (int d = 0; d < EE; d++) wv[d] = wp[(size_t)d * IO + io];
    __shared__ float sne[128 * EE];
    for (int n0 = 0; n0 < NN; n0 += 128) {
        __syncthreads();
        for (int t = threadIdx.x; t < 128 * EE; t += 256) sne[t] = ne[n0 * EE + t];
        __syncthreads();
        for (int nn = 0; nn < 128; nn++) {
            float v = 0.0f;
            #pragma unroll
            for (int d = 0; d < EE; d++) v += sne[nn * EE + d] * wv[d];
            g_W[(size_t)(n0 + nn) * IO + io] = v;
        }
    }
}

__global__ void k_bias(const float* __restrict__ ne, const float* __restrict__ bp, int O) {
    int n = blockIdx.x, o = threadIdx.x;
    float v = 0.0f;
    #pragma unroll
    for (int d = 0; d < EE; d++) v += ne[n * EE + d] * bp[d * O + o];
    g_BIAS[n * O + o] = v;
}

// ================ transpose + hi/lo split: B operand build =======================
// src [b][m][64] (x or state). Output d{hi,lo}[j=b*64+c][m], m contiguous.
// zmul: multiply by z = g_ZR[m][b*128 + c] (z part, c<64).
__global__ __launch_bounds__(256) void k_trans(const float* __restrict__ src,
                                               __nv_bfloat16* __restrict__ dhi,
                                               __nv_bfloat16* __restrict__ dlo,
                                               int zmul) {
    __shared__ float tile[64][68];
    int b = blockIdx.y, m0 = blockIdx.x * 64, tid = threadIdx.x;
    #pragma unroll
    for (int i = 0; i < 4; i++) {
        int id = i * 256 + tid;                 // 1024 float4 loads
        int r = id >> 4, c4 = id & 15;
        float4 v = *reinterpret_cast<const float4*>(
            src + ((size_t)b * NN + m0 + r) * 64 + c4 * 4);
        if (zmul) {
            float4 z = *reinterpret_cast<const float4*>(
                g_ZR + (size_t)(m0 + r) * XGPITCH + b * CC + c4 * 4);
            v.x *= z.x; v.y *= z.y; v.z *= z.z; v.w *= z.w;
        }
        *reinterpret_cast<float4*>(&tile[r][c4 * 4]) = v;
    }
    __syncthreads();
    int c = tid >> 2, mg = (tid & 3) * 16;
    uint32_t hi[8], lo[8];
    #pragma unroll
    for (int p = 0; p < 8; p++) {
        float v0 = tile[mg + 2 * p][c], v1 = tile[mg + 2 * p + 1][c];
        __nv_bfloat16 h0 = __float2bfloat16(v0);
        __nv_bfloat16 h1 = __float2bfloat16(v1);
        float l0 = v0 - __bfloat162float(h0);
        float l1 = v1 - __bfloat162float(h1);
        __nv_bfloat162 hp; hp.x = h0; hp.y = h1;
        __nv_bfloat162 lp = __floats2bfloat162_rn(l0, l1);
        hi[p] = *reinterpret_cast<uint32_t*>(&hp);
        lo[p] = *reinterpret_cast<uint32_t*>(&lp);
    }
    size_t o = (size_t)(b * 64 + c) * NN + m0 + mg;
    *reinterpret_cast<uint4*>(dhi + o)     = make_uint4(hi[0], hi[1], hi[2], hi[3]);
    *reinterpret_cast<uint4*>(dhi + o + 8) = make_uint4(hi[4], hi[5], hi[6], hi[7]);
    *reinterpret_cast<uint4*>(dlo + o)     = make_uint4(lo[0], lo[1], lo[2], lo[3]);
    *reinterpret_cast<uint4*>(dlo + o + 8) = make_uint4(lo[4], lo[5], lo[6], lo[7]);
}

// ================ big GEMM via mma.sync bf16, split-precision (3 terms) ==========
// C[4096 x 4096] = S @ B^T, A = S{hi,lo} row-major K-contig, B = {hi,lo} [j][k].
// Output col j -> XG[m][ (j>>6)*128 + coff + (j&63) ].
#define STAGE_BYTES (4 * 128 * 128)   // 4 matrices x 128 rows x 128B = 64 KB
#define OFF_ALO (128 * 128)
#define OFF_BHI (2 * 128 * 128)
#define OFF_BLO (3 * 128 * 128)
#define GEMM_SMEM (3 * STAGE_BYTES)   // 192 KB

__device__ __forceinline__ void load_stage(uint32_t base, int kt, int tid,
        const __nv_bfloat16* Ah, const __nv_bfloat16* Al,
        const __nv_bfloat16* Bh, const __nv_bfloat16* Bl) {
    #pragma unroll
    for (int i = 0; i < 4; i++) {
        int id = i * 256 + tid;
        int r = id >> 3, c = id & 7;
        uint32_t off = (uint32_t)(r * 128 + c * 16) ^ (uint32_t)((r & 7) << 4);
        size_t g = (size_t)r * NN + kt * 64 + c * 8;
        cpa16(base + off,            Ah + g);
        cpa16(base + OFF_ALO + off,  Al + g);
        cpa16(base + OFF_BHI + off,  Bh + g);
        cpa16(base + OFF_BLO + off,  Bl + g);
    }
    CP_COMMIT();
}

__global__ __launch_bounds__(256, 1) void k_hgemm(
        const __nv_bfloat16* __restrict__ Bhi,
        const __nv_bfloat16* __restrict__ Blo,
        int coff) {
    extern __shared__ char dsm[];
    uint32_t sb = smem_u32(dsm);
    int tid = threadIdx.x, lane = tid & 31, wid = tid >> 5;
    int bn = blockIdx.x, bm = blockIdx.y;

    const __nv_bfloat16* Ah = g_Shi + (size_t)(bm * 128) * NN;
    const __nv_bfloat16* Al = g_Slo + (size_t)(bm * 128) * NN;
    const __nv_bfloat16* Bh = Bhi + (size_t)(bn * 128) * NN;
    const __nv_bfloat16* Bl = Blo + (size_t)(bn * 128) * NN;

    int warp_m = (wid >> 2) * 64;    // 2 warps in M
    int warp_n = (wid & 3) * 32;     // 4 warps in N
    float acc[4][4][4] = {};         // [mt][nt8][frag]

    load_stage(sb, 0, tid, Ah, Al, Bh, Bl);
    load_stage(sb + STAGE_BYTES, 1, tid, Ah, Al, Bh, Bl);

    const int NKT = NN / 64;         // 64
    int lrowA = lane & 15, lgrp = lane >> 4;

    for (int kt = 0; kt < NKT; kt++) {
        CP_WAIT1();
        __syncthreads();
        if (kt + 2 < NKT)
            load_stage(sb + ((kt + 2) % 3) * STAGE_BYTES, kt + 2, tid, Ah, Al, Bh, Bl);
        else
            CP_COMMIT();             // keep group counting uniform

        uint32_t base = sb + (kt % 3) * STAGE_BYTES;
        #pragma unroll
        for (int k16 = 0; k16 < 4; k16++) {
            uint32_t ahi[4][4], alo[4][4], bhi[4][2], blo[4][2];
            #pragma unroll
            for (int mt = 0; mt < 4; mt++) {
                int r = warp_m + mt * 16 + lrowA;
                uint32_t off = (uint32_t)(r * 128 + (k16 * 2 + lgrp) * 16)
                             ^ (uint32_t)((r & 7) << 4);
                LDSM4(ahi[mt][0], ahi[mt][1], ahi[mt][2], ahi[mt][3], base + off);
                LDSM4(alo[mt][0], alo[mt][1], alo[mt][2], alo[mt][3], base + OFF_ALO + off);
            }
            #pragma unroll
            for (int ng = 0; ng < 2; ng++) {
                int r = warp_n + ng * 16 + lrowA;
                uint32_t off = (uint32_t)(r * 128 + (k16 * 2 + lgrp) * 16)
                             ^ (uint32_t)((r & 7) << 4);
                uint32_t t0, t1, t2, t3;
                LDSM4(t0, t1, t2, t3, base + OFF_BHI + off);
                bhi[ng * 2][0] = t0; bhi[ng * 2][1] = t2;
                bhi[ng * 2 + 1][0] = t1; bhi[ng * 2 + 1][1] = t3;
                LDSM4(t0, t1, t2, t3, base + OFF_BLO + off);
                blo[ng * 2][0] = t0; blo[ng * 2][1] = t2;
                blo[ng * 2 + 1][0] = t1; blo[ng * 2 + 1][1] = t3;
            }
            #pragma unroll
            for (int mt = 0; mt < 4; mt++)
                #pragma unroll
                for (int nt = 0; nt < 4; nt++) {
                    MMA_BF16(acc[mt][nt], ahi[mt], bhi[nt]);
                    MMA_BF16(acc[mt][nt], ahi[mt], blo[nt]);
                    MMA_BF16(acc[mt][nt], alo[mt], bhi[nt]);
                }
        }
    }

    // epilogue: C fragment (row = lane>>2 [+8], col = 2*(lane&3) [+1])
    int row0 = bm * 128 + warp_m + (lane >> 2);
    #pragma unroll
    for (int mt = 0; mt < 4; mt++) {
        #pragma unroll
        for (int nt = 0; nt < 4; nt++) {
            int j = bn * 128 + warp_n + nt * 8 + (lane & 3) * 2;
            int b = j >> 6, c = j & 63;
            float* p = g_XG + (size_t)(row0 + mt * 16) * XGPITCH + b * CC + coff + c;
            *reinterpret_cast<float2*>(p) = make_float2(acc[mt][nt][0], acc[mt][nt][1]);
            *reinterpret_cast<float2*>(p + (size_t)8 * XGPITCH) =
                make_float2(acc[mt][nt][2], acc[mt][nt][3]);
        }
    }
}

// ================ per-node gate GEMM + sigmoid ===================================
__global__ __launch_bounds__(256) void k_node_gate() {
    int n = blockIdx.x, tid = threadIdx.x;
    __shared__ float Xs[BB][132];
    __shared__ float Ws[16][132];

    #pragma unroll
    for (int p = 0; p < 8; p++) {
        int f = tid + p * 256;
        int b = f >> 5, i4 = (f & 31) << 2;
        *reinterpret_cast<float4*>(&Xs[b][i4]) =
            *reinterpret_cast<const float4*>(g_XG + (size_t)n * XGPITCH + b * CC + i4);
    }

    int tb = (tid >> 4) << 2;
    int tj = (tid & 15) << 3;
    float acc[4][8] = {};

    for (int i0 = 0; i0 < CC; i0 += 16) {
        __syncthreads();
        #pragma unroll
        for (int p = 0; p < 2; p++) {
            int f = tid + p * 256;
            int k = f >> 5, j4 = (f & 31) << 2;
            *reinterpret_cast<float4*>(&Ws[k][j4]) =
                *reinterpret_cast<const float4*>(g_W + (size_t)n * (CC * CC) + (i0 + k) * CC + j4);
        }
        __syncthreads();
        #pragma unroll
        for (int k = 0; k < 16; k++) {
            float a[4], bv[8];
            #pragma unroll
            for (int bb = 0; bb < 4; bb++) a[bb] = Xs[tb + bb][i0 + k];
            *reinterpret_cast<float4*>(&bv[0]) = *reinterpret_cast<const float4*>(&Ws[k][tj]);
            *reinterpret_cast<float4*>(&bv[4]) = *reinterpret_cast<const float4*>(&Ws[k][tj + 4]);
            #pragma unroll
            for (int bb = 0; bb < 4; bb++)
                #pragma unroll
                for (int jj = 0; jj < 8; jj++)
                    acc[bb][jj] += a[bb] * bv[jj];
        }
    }

    float bias[8];
    *reinterpret_cast<float4*>(&bias[0]) = *reinterpret_cast<const float4*>(g_BIAS + n * CC + tj);
    *reinterpret_cast<float4*>(&bias[4]) = *reinterpret_cast<const float4*>(g_BIAS + n * CC + tj + 4);
    #pragma unroll
    for (int bb = 0; bb < 4; bb++) {
        float y[8];
        #pragma unroll
        for (int jj = 0; jj < 8; jj++) {
            float v = acc[bb][jj] + bias[jj];
            y[jj] = 1.0f / (1.0f + __expf(-v));
        }
        float* dst = g_ZR + (size_t)n * XGPITCH + (tb + bb) * CC + tj;
        *reinterpret_cast<float4*>(dst) = make_float4(y[0], y[1], y[2], y[3]);
        *reinterpret_cast<float4*>(dst + 4) = make_float4(y[4], y[5], y[6], y[7]);
    }
}

// ================ per-node update GEMM + tanh + GRU combine ======================
__global__ __launch_bounds__(256) void k_node_final(const float* __restrict__ st,
                                                    float* __restrict__ out) {
    int n = blockIdx.x, tid = threadIdx.x;
    __shared__ float Xs[BB][132];
    __shared__ float Ws[16][68];

    #pragma unroll
    for (int p = 0; p < 8; p++) {
        int f = tid + p * 256;
        int b = f >> 5, i4 = (f & 31) << 2;
        *reinterpret_cast<float4*>(&Xs[b][i4]) =
            *reinterpret_cast<const float4*>(g_XG + (size_t)n * XGPITCH + b * CC + i4);
    }

    int tb = (tid >> 4) << 2;
    int to = (tid & 15) << 2;
    float acc[4][4] = {};

    for (int i0 = 0; i0 < CC; i0 += 16) {
        __syncthreads();
        {
            int k = tid >> 4, o4 = (tid & 15) << 2;
            *reinterpret_cast<float4*>(&Ws[k][o4]) =
                *reinterpret_cast<const float4*>(g_W + (size_t)n * (CC * DH) + (i0 + k) * DH + o4);
        }
        __syncthreads();
        #pragma unroll
        for (int k = 0; k < 16; k++) {
            float a[4], bv[4];
            #pragma unroll
            for (int bb = 0; bb < 4; bb++) a[bb] = Xs[tb + bb][i0 + k];
            *reinterpret_cast<float4*>(&bv[0]) = *reinterpret_cast<const float4*>(&Ws[k][to]);
            #pragma unroll
            for (int bb = 0; bb < 4; bb++)
                #pragma unroll
                for (int oo = 0; oo < 4; oo++)
                    acc[bb][oo] += a[bb] * bv[oo];
        }
    }

    float bias[4];
    *reinterpret_cast<float4*>(&bias[0]) = *reinterpret_cast<const float4*>(g_BIAS + n * DH + to);
    #pragma unroll
    for (int bb = 0; bb < 4; bb++) {
        int b = tb + bb;
        float4 r4 = *reinterpret_cast<const float4*>(g_ZR + (size_t)n * XGPITCH + b * CC + DH + to);
        float4 s4 = *reinterpret_cast<const float4*>(st + ((size_t)b * NN + n) * DH + to);
        float hc0 = tanhf(acc[bb][0] + bias[0]);
        float hc1 = tanhf(acc[bb][1] + bias[1]);
        float hc2 = tanhf(acc[bb][2] + bias[2]);
        float hc3 = tanhf(acc[bb][3] + bias[3]);
        float4 h;
        h.x = r4.x * s4.x + (1.0f - r4.x) * hc0;
        h.y = r4.y * s4.y + (1.0f - r4.y) * hc1;
        h.z = r4.z * s4.z + (1.0f - r4.z) * hc2;
        h.w = r4.w * s4.w + (1.0f - r4.w) * hc3;
        *reinterpret_cast<float4*>(out + ((size_t)b * NN + n) * DH + to) = h;
    }
}

// ================ launch =========================================================
extern "C" void kernel_launch(void* const* d_in, const int* in_sizes, int n_in,
                              void* d_out, int out_size) {
    const float* x   = (const float*)d_in[0];
    const float* st  = (const float*)d_in[1];
    const float* ne  = (const float*)d_in[2];
    const float* gwp = (const float*)d_in[3];
    const float* gbp = (const float*)d_in[4];
    const float* uwp = (const float*)d_in[5];
    const float* ubp = (const float*)d_in[6];
    float* out = (float*)d_out;

    static int smem_set = 0;
    if (!smem_set) {
        cudaFuncSetAttribute(k_hgemm, cudaFuncAttributeMaxDynamicSharedMemorySize, GEMM_SMEM);
        smem_set = 1;
    }

    __nv_bfloat16 *bxh, *bxl, *bsh, *bsl;
    cudaGetSymbolAddress((void**)&bxh, g_BXhi);
    cudaGetSymbolAddress((void**)&bxl, g_BXlo);
    cudaGetSymbolAddress((void**)&bsh, g_BShi);
    cudaGetSymbolAddress((void**)&bsl, g_BSlo);

    dim3 ggrid(NN / 128, NN / 128);

    k_supports<<<NN, 256>>>(ne);
    k_mkweights<<<(CC * CC) / 256, 256>>>(ne, gwp, CC * CC);
    k_bias<<<NN, CC>>>(ne, gbp, CC);

    // B operands: x^T (shared by both passes) and state^T
    k_trans<<<dim3(NN / 64, BB), 256>>>(x, bxh, bxl, 0);
    k_trans<<<dim3(NN / 64, BB), 256>>>(st, bsh, bsl, 0);

    // gate path: XG[:, :, 0:64] = S@x  (reused by update pass), XG[:, :, 64:128] = S@state
    k_hgemm<<<ggrid, 256, GEMM_SMEM>>>(bxh, bxl, 0);
    k_hgemm<<<ggrid, 256, GEMM_SMEM>>>(bsh, bsl, 64);
    k_node_gate<<<NN, 256>>>();

    // update path: rebuild state^T as (z*state)^T, redo right half only
    k_trans<<<dim3(NN / 64, BB), 256>>>(st, bsh, bsl, 1);
    k_mkweights<<<(CC * DH) / 256, 256>>>(ne, uwp, CC * DH);
    k_bias<<<NN, DH>>>(ne, ubp, DH);
    k_hgemm<<<ggrid, 256, GEMM_SMEM>>>(bsh, bsl, 64);
    k_node_final<<<NN, 256>>>(st, out);
}